// round 1
// baseline (speedup 1.0000x reference)
#include <cuda_runtime.h>
#include <cuda_bf16.h>

// ChamferLoss: p,q shape (2,64,1024,4) f32; use components 1..3.
// For each of CB=128 (c,b) pairs: D2[n][m] = |p3_n - q3_m|^2,
// dist = sqrt(max(D2,0)+1e-12); out = sum over pairs of
// (sum_n min_m dist + sum_m min_n dist).
//
// Strategy: sqrt/min commute (monotone), so track min of half-d2:
//   v = 0.5|q|^2 - p.q           (row-relative; add 0.5|p|^2 at the end)
//   u = v + 0.5|p|^2             (full half-d2, for column mins)
// Per 32-pair chunk per row: 3 FMA + 1 FADD + 2 FMNMX. No sqrt in hot loop.
// One CTA per pair. Column mins merged across warps via shared atomicMin on
// uint bits (values clamped >= 0, so bit order == float order). Fully
// deterministic: exact mins, fixed-order sums, per-CTA partials reduced by a
// second kernel.

#define NPTS   1024
#define THREADS 256
#define NWARPS   8
#define ROWS_PER_WARP 128
#define RGROUP   4
#define CB_MAX 128

__device__ float g_partials[CB_MAX];

__global__ __launch_bounds__(THREADS, 1)
void chamfer_pair_kernel(const float* __restrict__ p, const float* __restrict__ q) {
    __shared__ float qx_s[NPTS], qy_s[NPTS], qz_s[NPTS], qs_s[NPTS];
    __shared__ float px_s[NPTS], py_s[NPTS], pz_s[NPTS], ps_s[NPTS];
    __shared__ unsigned colmin_sh[NPTS];
    __shared__ float warp_rowsum[NWARPS];
    __shared__ float warp_colsum[NWARPS];

    const int cb  = blockIdx.x;
    const int tid = threadIdx.x;
    const float4* __restrict__ qp = reinterpret_cast<const float4*>(q) + (size_t)cb * NPTS;
    const float4* __restrict__ pp = reinterpret_cast<const float4*>(p) + (size_t)cb * NPTS;

    // Stage both point sets in SMEM (SoA). Pre-negate p and precompute half
    // squared norms so the hot loop is a pure FMA chain.
    for (int i = tid; i < NPTS; i += THREADS) {
        float4 v = qp[i];
        qx_s[i] = v.y; qy_s[i] = v.z; qz_s[i] = v.w;
        qs_s[i] = 0.5f * (v.y * v.y + v.z * v.z + v.w * v.w);
        float4 u = pp[i];
        px_s[i] = -u.y; py_s[i] = -u.z; pz_s[i] = -u.w;
        ps_s[i] = 0.5f * (u.y * u.y + u.z * u.z + u.w * u.w);
        colmin_sh[i] = 0x7f800000u;  // +inf bits
    }
    __syncthreads();

    const int warp = tid >> 5;
    const int lane = tid & 31;
    const float INF = __int_as_float(0x7f800000);

    // Per-lane column mins: lane covers columns (j*32 + lane), j = 0..31.
    float colmin[32];
    #pragma unroll
    for (int j = 0; j < 32; ++j) colmin[j] = INF;

    float rowsum = 0.0f;
    const int row0 = warp * ROWS_PER_WARP;

    for (int rg = 0; rg < ROWS_PER_WARP; rg += RGROUP) {
        float pnx[RGROUP], pny[RGROUP], pnz[RGROUP], psq[RGROUP], rmin[RGROUP];
        #pragma unroll
        for (int r = 0; r < RGROUP; ++r) {
            int row = row0 + rg + r;
            pnx[r] = px_s[row];   // broadcast LDS, conflict-free
            pny[r] = py_s[row];
            pnz[r] = pz_s[row];
            psq[r] = ps_s[row];
            rmin[r] = INF;
        }
        #pragma unroll
        for (int j = 0; j < 32; ++j) {
            int c = (j << 5) + lane;
            float x = qx_s[c], y = qy_s[c], z = qz_s[c], s = qs_s[c];
            #pragma unroll
            for (int r = 0; r < RGROUP; ++r) {
                float t = fmaf(pnx[r], x, s);   // 0.5|q|^2 - px*qx
                t = fmaf(pny[r], y, t);
                t = fmaf(pnz[r], z, t);
                rmin[r]   = fminf(rmin[r], t);             // row-relative min
                colmin[j] = fminf(colmin[j], t + psq[r]);  // full half-d2 min
            }
        }
        // Reduce row mins across lanes; sqrt only once per row.
        #pragma unroll
        for (int r = 0; r < RGROUP; ++r) {
            float m = rmin[r];
            #pragma unroll
            for (int off = 16; off > 0; off >>= 1)
                m = fminf(m, __shfl_xor_sync(0xffffffffu, m, off));
            float d2 = 2.0f * (m + psq[r]);
            rowsum += sqrtf(fmaxf(d2, 0.0f) + 1e-12f);  // same on all lanes
        }
    }

    // Merge per-warp column mins (clamped >= 0 so uint bit order == float order).
    #pragma unroll
    for (int j = 0; j < 32; ++j) {
        float v = fmaxf(colmin[j], 0.0f);
        atomicMin(&colmin_sh[(j << 5) + lane], __float_as_uint(v));
    }
    if (lane == 0) warp_rowsum[warp] = rowsum;
    __syncthreads();

    // Column distance sums.
    float csum = 0.0f;
    for (int i = tid; i < NPTS; i += THREADS) {
        float v = __uint_as_float(colmin_sh[i]);  // already clamped >= 0
        csum += sqrtf(2.0f * v + 1e-12f);
    }
    #pragma unroll
    for (int off = 16; off > 0; off >>= 1)
        csum += __shfl_xor_sync(0xffffffffu, csum, off);
    if (lane == 0) warp_colsum[warp] = csum;
    __syncthreads();

    if (tid == 0) {
        float total = 0.0f;
        #pragma unroll
        for (int w = 0; w < NWARPS; ++w) total += warp_rowsum[w] + warp_colsum[w];
        g_partials[cb] = total;
    }
}

__global__ void final_reduce_kernel(float* __restrict__ out, int cb_count) {
    __shared__ float s[4];
    int t = threadIdx.x;  // 128 threads
    float v = (t < cb_count) ? g_partials[t] : 0.0f;
    #pragma unroll
    for (int off = 16; off > 0; off >>= 1)
        v += __shfl_xor_sync(0xffffffffu, v, off);
    if ((t & 31) == 0) s[t >> 5] = v;
    __syncthreads();
    if (t == 0) out[0] = s[0] + s[1] + s[2] + s[3];
}

extern "C" void kernel_launch(void* const* d_in, const int* in_sizes, int n_in,
                              void* d_out, int out_size) {
    const float* p = (const float*)d_in[0];
    const float* q = (const float*)d_in[1];
    float* out = (float*)d_out;

    int cb = in_sizes[0] / (NPTS * 4);   // = 128 for (2,64,1024,4)
    if (cb > CB_MAX) cb = CB_MAX;

    chamfer_pair_kernel<<<cb, THREADS>>>(p, q);
    final_reduce_kernel<<<1, 128>>>(out, cb);
}

// round 2
// speedup vs baseline: 1.1354x; 1.1354x over previous
#include <cuda_runtime.h>
#include <cuda_bf16.h>

// ChamferLoss: p,q (2,64,1024,4) f32, components 1..3.
// u = 0.5*|p_n - q_m|^2 tracked directly (norms folded into FMA accumulator
// init), sqrt hoisted outside the mins (monotone). Packed f32x2 math: one
// fma-pipe op computes 2 column-pairs -> 2 fma-pipe ops per distance instead
// of 4. Column mins merged via shared atomicMin on uint bits (values clamped
// >=0 so bit order == float order). Fully deterministic.

#define NPTS    1024
#define THREADS 256
#define NWARPS  8
#define ROWS_PER_WARP 128
#define RG      8          // rows per register group
#define CB_MAX  128

#define PACK2(d, lo, hi) \
    asm("mov.b64 %0, {%1,%2};" : "=l"(d) : "f"(lo), "f"(hi))
#define UNPACK2(lo, hi, s) \
    asm("mov.b64 {%0,%1}, %2;" : "=f"(lo), "=f"(hi) : "l"(s))
#define FMA2(d, a, b, c) \
    asm("fma.rn.f32x2 %0, %1, %2, %3;" : "=l"(d) : "l"(a), "l"(b), "l"(c))
#define ADD2(d, a, b) \
    asm("add.rn.f32x2 %0, %1, %2;" : "=l"(d) : "l"(a), "l"(b))

__device__ float g_partials[CB_MAX];

__global__ __launch_bounds__(THREADS, 1)
void chamfer_pair_kernel(const float* __restrict__ p, const float* __restrict__ q) {
    __shared__ __align__(16) float qx_s[NPTS], qy_s[NPTS], qz_s[NPTS], qs_s[NPTS];
    __shared__ __align__(16) float px_s[NPTS], py_s[NPTS], pz_s[NPTS], ps_s[NPTS];
    __shared__ unsigned colmin_sh[NPTS];
    __shared__ float warp_rowsum[NWARPS];
    __shared__ float warp_colsum[NWARPS];

    const int cb  = blockIdx.x;
    const int tid = threadIdx.x;
    const float4* __restrict__ qp = reinterpret_cast<const float4*>(q) + (size_t)cb * NPTS;
    const float4* __restrict__ pp = reinterpret_cast<const float4*>(p) + (size_t)cb * NPTS;

    // Stage both point sets (SoA). p pre-negated; half squared norms precomputed.
    for (int i = tid; i < NPTS; i += THREADS) {
        float4 v = qp[i];
        qx_s[i] = v.y; qy_s[i] = v.z; qz_s[i] = v.w;
        qs_s[i] = 0.5f * (v.y * v.y + v.z * v.z + v.w * v.w);
        float4 u = pp[i];
        px_s[i] = -u.y; py_s[i] = -u.z; pz_s[i] = -u.w;
        ps_s[i] = 0.5f * (u.y * u.y + u.z * u.z + u.w * u.w);
        colmin_sh[i] = 0x7f800000u;  // +inf bits
    }
    __syncthreads();

    const int warp = tid >> 5;
    const int lane = tid & 31;
    const float INF = __int_as_float(0x7f800000);

    // Lane owns columns (j2*64 + lane*2 + {0,1}), j2 = 0..15.
    float colmin[32];
    #pragma unroll
    for (int j = 0; j < 32; ++j) colmin[j] = INF;

    float rowsum = 0.0f;
    const int row0 = warp * ROWS_PER_WARP;

    for (int rg = 0; rg < ROWS_PER_WARP; rg += RG) {
        unsigned long long pnx2[RG], pny2[RG], pnz2[RG], psq2[RG];
        float rmin[RG];
        #pragma unroll
        for (int r = 0; r < RG; ++r) {
            int row = row0 + rg + r;
            float a = px_s[row], b = py_s[row], c = pz_s[row], d = ps_s[row];
            PACK2(pnx2[r], a, a);
            PACK2(pny2[r], b, b);
            PACK2(pnz2[r], c, c);
            PACK2(psq2[r], d, d);
            rmin[r] = INF;
        }
        #pragma unroll
        for (int j2 = 0; j2 < 16; ++j2) {
            const int base = (j2 << 6) + (lane << 1);   // 8B-aligned
            unsigned long long xx2 = *reinterpret_cast<const unsigned long long*>(qx_s + base);
            unsigned long long yy2 = *reinterpret_cast<const unsigned long long*>(qy_s + base);
            unsigned long long zz2 = *reinterpret_cast<const unsigned long long*>(qz_s + base);
            unsigned long long ss2 = *reinterpret_cast<const unsigned long long*>(qs_s + base);
            #pragma unroll
            for (int r = 0; r < RG; ++r) {
                unsigned long long acc;
                ADD2(acc, ss2, psq2[r]);          // 0.5|q|^2 + 0.5|p|^2 (x2 cols)
                FMA2(acc, pnx2[r], xx2, acc);     // - px*qx
                FMA2(acc, pny2[r], yy2, acc);
                FMA2(acc, pnz2[r], zz2, acc);     // acc = 0.5*d2 for 2 columns
                float u0, u1;
                UNPACK2(u0, u1, acc);
                colmin[2 * j2]     = fminf(colmin[2 * j2],     u0);
                colmin[2 * j2 + 1] = fminf(colmin[2 * j2 + 1], u1);
                rmin[r] = fminf(rmin[r], fminf(u0, u1));
            }
        }
        // Row mins across lanes; one sqrt per row.
        #pragma unroll
        for (int r = 0; r < RG; ++r) {
            float m = rmin[r];
            #pragma unroll
            for (int off = 16; off > 0; off >>= 1)
                m = fminf(m, __shfl_xor_sync(0xffffffffu, m, off));
            rowsum += sqrtf(fmaxf(2.0f * m, 0.0f) + 1e-12f);  // same on all lanes
        }
    }

    // Merge per-warp column mins (clamped >= 0 -> uint order == float order).
    #pragma unroll
    for (int j2 = 0; j2 < 16; ++j2) {
        #pragma unroll
        for (int k = 0; k < 2; ++k) {
            int c = (j2 << 6) + (lane << 1) + k;
            float v = fmaxf(colmin[2 * j2 + k], 0.0f);
            atomicMin(&colmin_sh[c], __float_as_uint(v));
        }
    }
    if (lane == 0) warp_rowsum[warp] = rowsum;
    __syncthreads();

    // Column distance sums.
    float csum = 0.0f;
    for (int i = tid; i < NPTS; i += THREADS) {
        float v = __uint_as_float(colmin_sh[i]);  // already clamped >= 0
        csum += sqrtf(2.0f * v + 1e-12f);
    }
    #pragma unroll
    for (int off = 16; off > 0; off >>= 1)
        csum += __shfl_xor_sync(0xffffffffu, csum, off);
    if (lane == 0) warp_colsum[warp] = csum;
    __syncthreads();

    if (tid == 0) {
        float total = 0.0f;
        #pragma unroll
        for (int w = 0; w < NWARPS; ++w) total += warp_rowsum[w] + warp_colsum[w];
        g_partials[cb] = total;
    }
}

__global__ void final_reduce_kernel(float* __restrict__ out, int cb_count) {
    __shared__ float s[4];
    int t = threadIdx.x;  // 128 threads
    float v = (t < cb_count) ? g_partials[t] : 0.0f;
    #pragma unroll
    for (int off = 16; off > 0; off >>= 1)
        v += __shfl_xor_sync(0xffffffffu, v, off);
    if ((t & 31) == 0) s[t >> 5] = v;
    __syncthreads();
    if (t == 0) out[0] = s[0] + s[1] + s[2] + s[3];
}

extern "C" void kernel_launch(void* const* d_in, const int* in_sizes, int n_in,
                              void* d_out, int out_size) {
    const float* p = (const float*)d_in[0];
    const float* q = (const float*)d_in[1];
    float* out = (float*)d_out;

    int cb = in_sizes[0] / (NPTS * 4);   // = 128 for (2,64,1024,4)
    if (cb > CB_MAX) cb = CB_MAX;

    chamfer_pair_kernel<<<cb, THREADS>>>(p, q);
    final_reduce_kernel<<<1, 128>>>(out, cb);
}